// round 4
// baseline (speedup 1.0000x reference)
#include <cuda_runtime.h>
#include <cmath>
#include <cstdint>

#define N_LEVELS 16
#define TBL_STRIDE 524288u   // 2^19 entries per level
#define OUT_COMPS 35         // 3 (x passthrough) + 16*2 feats
#define THREADS 256
#define HASH_MASK 524287u    // 2^19 - 1; levels >= 6 are always fully hashed
#define NBUCKETS 262144      // 64^3 Morton buckets
#define SCAN_THREADS 1024
#define NPTS_MAX (1 << 20)

struct Params {
    float res[N_LEVELS];
    unsigned hms[N_LEVELS];
    unsigned long long magic[N_LEVELS];
};

// Scratch (static device allocations are allowed)
__device__ unsigned g_hist[NBUCKETS];
__device__ unsigned g_base[NBUCKETS];
__device__ float4   g_xs[NPTS_MAX];   // sorted {x,y,z, bitcast(orig_idx)}

// Lemire fastmod: n % d with M = 2^64/d + 1 (exact for all n < 2^32)
__device__ __forceinline__ unsigned fastmod(unsigned n, unsigned d, unsigned long long M) {
    unsigned long long low = M * (unsigned long long)n;
    return (unsigned)__umul64hi(low, (unsigned long long)d);
}

__device__ __forceinline__ unsigned expand_bits(unsigned v) {
    v &= 0x3FFu;
    v = (v | (v << 16)) & 0x30000FFu;
    v = (v | (v << 8))  & 0x300F00Fu;
    v = (v | (v << 4))  & 0x30C30C3u;
    v = (v | (v << 2))  & 0x9249249u;
    return v;
}

__device__ __forceinline__ unsigned bucket_of(float x0, float x1, float x2) {
    unsigned cx = min(63u, (unsigned)(x0 * 64.0f));
    unsigned cy = min(63u, (unsigned)(x1 * 64.0f));
    unsigned cz = min(63u, (unsigned)(x2 * 64.0f));
    return expand_bits(cx) | (expand_bits(cy) << 1) | (expand_bits(cz) << 2);
}

__global__ void zero_hist_kernel() {
    g_hist[blockIdx.x * 256 + threadIdx.x] = 0u;
}

__global__ void hist_kernel(const float* __restrict__ x, int npts) {
    const int i = blockIdx.x * 256 + threadIdx.x;
    if (i >= npts) return;
    const unsigned b = bucket_of(x[i * 3], x[i * 3 + 1], x[i * 3 + 2]);
    atomicAdd(&g_hist[b], 1u);
}

// Single-block exclusive scan of g_hist into g_base (262144 = 1024 * 256).
__global__ __launch_bounds__(SCAN_THREADS)
void scan_kernel() {
    __shared__ unsigned part[SCAN_THREADS];
    const int t = threadIdx.x;
    unsigned s = 0;
    for (int j = 0; j < NBUCKETS / SCAN_THREADS; j++)
        s += g_hist[t * (NBUCKETS / SCAN_THREADS) + j];
    part[t] = s;
    __syncthreads();
    // Hillis-Steele inclusive scan
    for (int off = 1; off < SCAN_THREADS; off <<= 1) {
        unsigned v = (t >= off) ? part[t - off] : 0u;
        __syncthreads();
        part[t] += v;
        __syncthreads();
    }
    unsigned run = part[t] - s;   // exclusive prefix of this thread's chunk
    for (int j = 0; j < NBUCKETS / SCAN_THREADS; j++) {
        const int idx = t * (NBUCKETS / SCAN_THREADS) + j;
        g_base[idx] = run;
        run += g_hist[idx];
    }
}

__global__ void scatter_kernel(const float* __restrict__ x, int npts) {
    const int i = blockIdx.x * 256 + threadIdx.x;
    if (i >= npts) return;
    const float x0 = x[i * 3], x1 = x[i * 3 + 1], x2 = x[i * 3 + 2];
    const unsigned b = bucket_of(x0, x1, x2);
    const unsigned pos = atomicAdd(&g_base[b], 1u);
    g_xs[pos] = make_float4(x0, x1, x2, __int_as_float(i));
}

__global__ __launch_bounds__(THREADS)
void hashgrid_kernel(const float2* __restrict__ tables,
                     float* __restrict__ out,
                     Params prm) {
    __shared__ float stage[THREADS * OUT_COMPS];

    const int si = blockIdx.x * THREADS + threadIdx.x;   // sorted index
    const float4 xs = g_xs[si];
    const float x0 = xs.x, x1 = xs.y, x2 = xs.z;
    const int p = __float_as_int(xs.w);                  // original point index

    float* my = &stage[threadIdx.x * OUT_COMPS];
    my[0] = x0; my[1] = x1; my[2] = x2;

    const unsigned P1 = 2654435761u;
    const unsigned P2 = 805459861u;

#pragma unroll
    for (int l = 0; l < N_LEVELS; l++) {
        const float r = prm.res[l];
        const float2* __restrict__ tb = tables + (size_t)l * TBL_STRIDE;

        const float xs0 = x0 * r, xs1 = x1 * r, xs2 = x2 * r;
        const float fl0 = floorf(xs0), fl1 = floorf(xs1), fl2 = floorf(xs2);
        const float fx = xs0 - fl0, fy = xs1 - fl1, fz = xs2 - fl2;

        const unsigned a0 = (unsigned)(int)fl0;
        const unsigned a1 = a0 + 1u;
        const unsigned b0 = (unsigned)(int)fl1 * P1;
        const unsigned c0 = (unsigned)(int)fl2 * P2;
        const unsigned hb[2] = {b0, b0 + P1};
        const unsigned hc[2] = {c0, c0 + P2};

        // e[n], n = ix | iy<<1 | iz<<2
        float2 e[8];

        if (l >= 6) {
            // Fully hashed: index = h & MASK. When a0 even, h(ix=1)=h(ix=0)^1
            // for every (iy,iz) pair -> {2k,2k+1} -> one float4 load.
            if ((a0 & 1u) == 0u) {
#pragma unroll
                for (int pr = 0; pr < 4; pr++) {
                    const int iy = pr & 1, iz = pr >> 1;
                    const unsigned m0 = (a0 ^ hb[iy] ^ hc[iz]) & HASH_MASK;
                    const float4 q = __ldcg((const float4*)tb + (m0 >> 1));
                    const float2 lo = make_float2(q.x, q.y);
                    const float2 hi = make_float2(q.z, q.w);
                    const bool odd = (m0 & 1u) != 0u;
                    const int n = (iy << 1) | (iz << 2);
                    e[n]     = odd ? hi : lo;
                    e[n | 1] = odd ? lo : hi;
                }
            } else {
#pragma unroll
                for (int pr = 0; pr < 4; pr++) {
                    const int iy = pr & 1, iz = pr >> 1;
                    const unsigned hbc = hb[iy] ^ hc[iz];
                    const int n = (iy << 1) | (iz << 2);
                    e[n]     = __ldcg(tb + ((a0 ^ hbc) & HASH_MASK));
                    e[n | 1] = __ldcg(tb + ((a1 ^ hbc) & HASH_MASK));
                }
            }
        } else {
            const unsigned d = prm.hms[l];
            const unsigned long long M = prm.magic[l];
#pragma unroll
            for (int pr = 0; pr < 4; pr++) {
                const int iy = pr & 1, iz = pr >> 1;
                const unsigned hbc = hb[iy] ^ hc[iz];
                const unsigned m0 = fastmod(a0 ^ hbc, d, M);
                const unsigned m1 = fastmod(a1 ^ hbc, d, M);
                const int n = (iy << 1) | (iz << 2);
                if ((m0 ^ m1) == 1u) {
                    const float4 q = __ldg((const float4*)tb + (m0 >> 1));
                    const float2 lo = make_float2(q.x, q.y);
                    const float2 hi = make_float2(q.z, q.w);
                    const bool odd = (m0 & 1u) != 0u;
                    e[n]     = odd ? hi : lo;
                    e[n | 1] = odd ? lo : hi;
                } else {
                    e[n]     = __ldg(tb + m0);
                    e[n | 1] = __ldg(tb + m1);
                }
            }
        }

        const float wx[2] = {1.0f - fx, fx};
        const float wy[2] = {1.0f - fy, fy};
        const float wz[2] = {1.0f - fz, fz};

        float acc0 = 0.0f, acc1 = 0.0f;
#pragma unroll
        for (int n = 0; n < 8; n++) {
            const float w = wx[n & 1] * wy[(n >> 1) & 1] * wz[n >> 2];
            acc0 = fmaf(e[n].x, w, acc0);
            acc1 = fmaf(e[n].y, w, acc1);
        }
        my[3 + 2 * l]     = acc0;
        my[3 + 2 * l + 1] = acc1;
    }

    __syncwarp();

    // Warp-cooperative scatter: for each of the warp's 32 rows, all lanes
    // copy the 35 floats of that row to its original-index output slot.
    // Each row (140B) spans ~2 lines -> ~4 wavefronts/row total.
    const int lane = threadIdx.x & 31;
    const float* warp_stage = &stage[(threadIdx.x & ~31) * OUT_COMPS];
#pragma unroll 4
    for (int r = 0; r < 32; r++) {
        const int pr = __shfl_sync(0xFFFFFFFFu, p, r);
        float* dst = out + (size_t)pr * OUT_COMPS;
        const float* src = warp_stage + r * OUT_COMPS;
        if (lane < OUT_COMPS)      dst[lane] = src[lane];
        if (lane < OUT_COMPS - 32) dst[lane + 32] = src[lane + 32];
    }
}

extern "C" void kernel_launch(void* const* d_in, const int* in_sizes, int n_in,
                              void* d_out, int out_size) {
    const float*  x      = (const float*)d_in[0];
    const float2* tables = (const float2*)d_in[1];
    float*        out    = (float*)d_out;

    // Level params via the exact same double-precision libm sequence as the
    // Python reference (same machine/libm => bit-identical results).
    Params prm;
    const double beta = exp((log(2048.0) - log(16.0)) / 15.0);
    for (int l = 0; l < N_LEVELS; l++) {
        const double r = floor(16.0 * pow(beta, (double)l));
        prm.res[l] = (float)r;
        const long long ri = (long long)r;
        long long h3 = ri * ri * ri;
        if (h3 > 524288LL) h3 = 524288LL;
        const unsigned d = (unsigned)h3;
        prm.hms[l] = d;
        prm.magic[l] = 0xFFFFFFFFFFFFFFFFull / d + 1ull;
    }

    const int npts = in_sizes[0] / 3;
    const int blocks = (npts + 255) / 256;

    zero_hist_kernel<<<NBUCKETS / 256, 256>>>();
    hist_kernel<<<blocks, 256>>>(x, npts);
    scan_kernel<<<1, SCAN_THREADS>>>();
    scatter_kernel<<<blocks, 256>>>(x, npts);
    hashgrid_kernel<<<(npts + THREADS - 1) / THREADS, THREADS>>>(tables, out, prm);
}

// round 6
// speedup vs baseline: 1.6707x; 1.6707x over previous
#include <cuda_runtime.h>
#include <cmath>
#include <cstdint>

#define N_LEVELS 16
#define TBL_STRIDE 524288u   // 2^19 entries per level
#define OUT_COMPS 35         // 3 (x passthrough) + 16*2 feats
#define THREADS 256
#define HASH_MASK 524287u    // 2^19 - 1; levels >= 6 are always fully hashed
#define NBUCKETS 32768       // 32^3 Morton buckets
#define SCAN_THREADS 1024
#define NPTS_MAX (1 << 20)

struct Params {
    float res[N_LEVELS];
    unsigned hms[N_LEVELS];
    unsigned long long magic[N_LEVELS];
};

// Scratch (static device arrays are allowed)
__device__ unsigned g_hist[NBUCKETS];
__device__ unsigned g_base[NBUCKETS];
__device__ float4   g_xs[NPTS_MAX];   // sorted {x,y,z, bitcast(orig_idx)}

// Lemire fastmod: n % d with M = 2^64/d + 1 (exact for all n < 2^32)
__device__ __forceinline__ unsigned fastmod(unsigned n, unsigned d, unsigned long long M) {
    unsigned long long low = M * (unsigned long long)n;
    return (unsigned)__umul64hi(low, (unsigned long long)d);
}

__device__ __forceinline__ unsigned expand_bits(unsigned v) {
    v &= 0x3FFu;
    v = (v | (v << 16)) & 0x30000FFu;
    v = (v | (v << 8))  & 0x300F00Fu;
    v = (v | (v << 4))  & 0x30C30C3u;
    v = (v | (v << 2))  & 0x9249249u;
    return v;
}

__device__ __forceinline__ unsigned bucket_of(float x0, float x1, float x2) {
    unsigned cx = min(31u, (unsigned)(x0 * 32.0f));
    unsigned cy = min(31u, (unsigned)(x1 * 32.0f));
    unsigned cz = min(31u, (unsigned)(x2 * 32.0f));
    return expand_bits(cx) | (expand_bits(cy) << 1) | (expand_bits(cz) << 2);
}

__global__ void zero_hist_kernel() {
    g_hist[blockIdx.x * 256 + threadIdx.x] = 0u;
}

__global__ void hist_kernel(const float* __restrict__ x, int npts) {
    const int i = blockIdx.x * 256 + threadIdx.x;
    if (i >= npts) return;
    const unsigned b = bucket_of(x[i * 3], x[i * 3 + 1], x[i * 3 + 2]);
    atomicAdd(&g_hist[b], 1u);
}

// Single-block exclusive scan of g_hist into g_base (32768 = 1024 * 32).
// Chunk-strided loads revisit the same L1 lines across iterations -> cheap.
__global__ __launch_bounds__(SCAN_THREADS)
void scan_kernel() {
    __shared__ unsigned part[SCAN_THREADS];
    const int t = threadIdx.x;
    const int C = NBUCKETS / SCAN_THREADS;   // 32
    unsigned s = 0;
#pragma unroll
    for (int j = 0; j < C; j++)
        s += g_hist[t * C + j];
    part[t] = s;
    __syncthreads();
    for (int off = 1; off < SCAN_THREADS; off <<= 1) {
        unsigned v = (t >= off) ? part[t - off] : 0u;
        __syncthreads();
        part[t] += v;
        __syncthreads();
    }
    unsigned run = part[t] - s;   // exclusive prefix of this thread's chunk
#pragma unroll
    for (int j = 0; j < C; j++) {
        const int idx = t * C + j;
        g_base[idx] = run;
        run += g_hist[idx];
    }
}

__global__ void scatter_kernel(const float* __restrict__ x, int npts) {
    const int i = blockIdx.x * 256 + threadIdx.x;
    if (i >= npts) return;
    const float x0 = x[i * 3], x1 = x[i * 3 + 1], x2 = x[i * 3 + 2];
    const unsigned b = bucket_of(x0, x1, x2);
    const unsigned pos = atomicAdd(&g_base[b], 1u);
    g_xs[pos] = make_float4(x0, x1, x2, __int_as_float(i));
}

__global__ __launch_bounds__(THREADS)
void hashgrid_kernel(const float2* __restrict__ tables,
                     float* __restrict__ out,
                     Params prm) {
    __shared__ float stage[THREADS * OUT_COMPS];

    const int si = blockIdx.x * THREADS + threadIdx.x;   // sorted index
    const float4 xsv = g_xs[si];
    const float x0 = xsv.x, x1 = xsv.y, x2 = xsv.z;
    const int p = __float_as_int(xsv.w);                 // original point index

    float* my = &stage[threadIdx.x * OUT_COMPS];
    my[0] = x0; my[1] = x1; my[2] = x2;

    const unsigned P1 = 2654435761u;
    const unsigned P2 = 805459861u;

#pragma unroll
    for (int l = 0; l < N_LEVELS; l++) {
        const float r = prm.res[l];
        const float2* __restrict__ tb = tables + (size_t)l * TBL_STRIDE;

        const float xs0 = x0 * r, xs1 = x1 * r, xs2 = x2 * r;
        const float fl0 = floorf(xs0), fl1 = floorf(xs1), fl2 = floorf(xs2);
        const float fx = xs0 - fl0, fy = xs1 - fl1, fz = xs2 - fl2;

        const unsigned a0 = (unsigned)(int)fl0;
        const unsigned a1 = a0 + 1u;
        const unsigned b0 = (unsigned)(int)fl1 * P1;
        const unsigned c0 = (unsigned)(int)fl2 * P2;
        const unsigned hb[2] = {b0, b0 + P1};
        const unsigned hc[2] = {c0, c0 + P2};

        // e[n], n = ix | iy<<1 | iz<<2
        float2 e[8];

        if (l >= 6) {
            // Fully hashed: index = h & MASK. When a0 even, h(ix=1)=h(ix=0)^1
            // for every (iy,iz) pair -> {2k,2k+1} -> one float4 load.
            if ((a0 & 1u) == 0u) {
#pragma unroll
                for (int pr = 0; pr < 4; pr++) {
                    const int iy = pr & 1, iz = pr >> 1;
                    const unsigned m0 = (a0 ^ hb[iy] ^ hc[iz]) & HASH_MASK;
                    const float4 q = __ldcg((const float4*)tb + (m0 >> 1));
                    const float2 lo = make_float2(q.x, q.y);
                    const float2 hi = make_float2(q.z, q.w);
                    const bool odd = (m0 & 1u) != 0u;
                    const int n = (iy << 1) | (iz << 2);
                    e[n]     = odd ? hi : lo;
                    e[n | 1] = odd ? lo : hi;
                }
            } else {
#pragma unroll
                for (int pr = 0; pr < 4; pr++) {
                    const int iy = pr & 1, iz = pr >> 1;
                    const unsigned hbc = hb[iy] ^ hc[iz];
                    const int n = (iy << 1) | (iz << 2);
                    e[n]     = __ldcg(tb + ((a0 ^ hbc) & HASH_MASK));
                    e[n | 1] = __ldcg(tb + ((a1 ^ hbc) & HASH_MASK));
                }
            }
        } else {
            const unsigned d = prm.hms[l];
            const unsigned long long M = prm.magic[l];
#pragma unroll
            for (int pr = 0; pr < 4; pr++) {
                const int iy = pr & 1, iz = pr >> 1;
                const unsigned hbc = hb[iy] ^ hc[iz];
                const unsigned m0 = fastmod(a0 ^ hbc, d, M);
                const unsigned m1 = fastmod(a1 ^ hbc, d, M);
                const int n = (iy << 1) | (iz << 2);
                if ((m0 ^ m1) == 1u) {
                    // Same aligned 16B pair: one float4 load.
                    const float4 q = (l < 3) ? __ldg((const float4*)tb + (m0 >> 1))
                                             : __ldcg((const float4*)tb + (m0 >> 1));
                    const float2 lo = make_float2(q.x, q.y);
                    const float2 hi = make_float2(q.z, q.w);
                    const bool odd = (m0 & 1u) != 0u;
                    e[n]     = odd ? hi : lo;
                    e[n | 1] = odd ? lo : hi;
                } else {
                    e[n]     = (l < 3) ? __ldg(tb + m0) : __ldcg(tb + m0);
                    e[n | 1] = (l < 3) ? __ldg(tb + m1) : __ldcg(tb + m1);
                }
            }
        }

        const float wx[2] = {1.0f - fx, fx};
        const float wy[2] = {1.0f - fy, fy};
        const float wz[2] = {1.0f - fz, fz};

        float acc0 = 0.0f, acc1 = 0.0f;
#pragma unroll
        for (int n = 0; n < 8; n++) {
            const float w = wx[n & 1] * wy[(n >> 1) & 1] * wz[n >> 2];
            acc0 = fmaf(e[n].x, w, acc0);
            acc1 = fmaf(e[n].y, w, acc1);
        }
        my[3 + 2 * l]     = acc0;
        my[3 + 2 * l + 1] = acc1;
    }

    __syncwarp();

    // Warp-cooperative scatter: all 32 lanes jointly copy each of the warp's
    // 32 rows (35 floats) to that row's original-index output slot.
    const int lane = threadIdx.x & 31;
    const float* warp_stage = &stage[(threadIdx.x & ~31) * OUT_COMPS];
#pragma unroll 4
    for (int r = 0; r < 32; r++) {
        const int pr = __shfl_sync(0xFFFFFFFFu, p, r);
        float* dst = out + (size_t)pr * OUT_COMPS;
        const float* src = warp_stage + r * OUT_COMPS;
        if (lane < OUT_COMPS)      dst[lane] = src[lane];
        if (lane < OUT_COMPS - 32) dst[lane + 32] = src[lane + 32];
    }
}

extern "C" void kernel_launch(void* const* d_in, const int* in_sizes, int n_in,
                              void* d_out, int out_size) {
    const float*  x      = (const float*)d_in[0];
    const float2* tables = (const float2*)d_in[1];
    float*        out    = (float*)d_out;

    // Level params via the exact same double-precision libm sequence as the
    // Python reference (same machine/libm => bit-identical results).
    Params prm;
    const double beta = exp((log(2048.0) - log(16.0)) / 15.0);
    for (int l = 0; l < N_LEVELS; l++) {
        const double r = floor(16.0 * pow(beta, (double)l));
        prm.res[l] = (float)r;
        const long long ri = (long long)r;
        long long h3 = ri * ri * ri;
        if (h3 > 524288LL) h3 = 524288LL;
        const unsigned d = (unsigned)h3;
        prm.hms[l] = d;
        prm.magic[l] = 0xFFFFFFFFFFFFFFFFull / d + 1ull;
    }

    const int npts = in_sizes[0] / 3;
    const int blocks = (npts + 255) / 256;

    zero_hist_kernel<<<NBUCKETS / 256, 256>>>();
    hist_kernel<<<blocks, 256>>>(x, npts);
    scan_kernel<<<1, SCAN_THREADS>>>();
    scatter_kernel<<<blocks, 256>>>(x, npts);
    hashgrid_kernel<<<(npts + THREADS - 1) / THREADS, THREADS>>>(tables, out, prm);
}